// round 3
// baseline (speedup 1.0000x reference)
#include <cuda_runtime.h>

#define MAXB     16384
#define HDIM     256
#define MAXNORM  0.996f           /* (1 - 4e-3)/sqrt(c), c=1 */
#define ART_CLIP (1.0f - 1e-5f)   /* artanh clip */
#define NORM_EPS 1e-15f

/* ------------------------------------------------------------------ */
/* Scratch (device globals; no allocation allowed)                     */
/* ------------------------------------------------------------------ */
__device__ float g_xd  [MAXB * 1711];
__device__ float g_xt  [MAXB * 1711];
__device__ float g_mx  [MAXB * 1024];
__device__ float g_ha  [MAXB * 1024];
__device__ float g_hb  [MAXB * 512];
__device__ float g_head[MAXB * HDIM];
__device__ float g_tail[MAXB * HDIM];
__device__ float g_mid [MAXB * HDIM];
__device__ float g_r1  [MAXB * 64];
__device__ float g_r2  [MAXB * 32];
__device__ float g_na  [MAXB];
__device__ float g_nb  [MAXB];
__device__ float g_nhead[MAXB];
__device__ float g_ntail[MAXB];
__device__ float g_nmid [MAXB];

/* ------------------------------------------------------------------ */
/* Block-wide sum over 256 threads; result returned to all threads     */
/* ------------------------------------------------------------------ */
__device__ __forceinline__ float blockSum(float v, float* sbuf)
{
    #pragma unroll
    for (int o = 16; o > 0; o >>= 1)
        v += __shfl_xor_sync(0xffffffffu, v, o);
    int w = threadIdx.x >> 5;
    if ((threadIdx.x & 31) == 0) sbuf[w] = v;
    __syncthreads();
    float r = ((sbuf[0] + sbuf[1]) + (sbuf[2] + sbuf[3]))
            + ((sbuf[4] + sbuf[5]) + (sbuf[6] + sbuf[7]));
    __syncthreads();
    return r;
}

/* ------------------------------------------------------------------ */
/* Prep: per-row zscore of each feature segment (ddof=1), concat,      */
/* expmap0. Stores x0 and its analytic norm tanh(n).                   */
/* One block (256 thr) per row.                                        */
/* ------------------------------------------------------------------ */
__global__ __launch_bounds__(256) void prep_kernel(
    const float* __restrict__ s0, const float* __restrict__ s1,
    const float* __restrict__ s2, const float* __restrict__ s3,
    int l0, int l1, int l2, int l3, int nseg, int D,
    float* __restrict__ xout, float* __restrict__ nout)
{
    __shared__ float srow[1712];
    __shared__ float sbuf[8];
    const int row = blockIdx.x, tid = threadIdx.x;
    const float* sp[4] = { s0, s1, s2, s3 };
    int          ln[4] = { l0, l1, l2, l3 };

    int off = 0;
    for (int sg = 0; sg < nseg; ++sg) {
        int L = ln[sg];
        const float* p = sp[sg] + (size_t)row * L;
        float s = 0.f, ss = 0.f;
        for (int i = tid; i < L; i += 256) { float v = p[i]; s += v; ss += v * v; }
        s  = blockSum(s,  sbuf);
        ss = blockSum(ss, sbuf);
        float m   = s / (float)L;
        float var = (ss - s * m) / (float)(L - 1);      /* ddof = 1 */
        float sd  = sqrtf(fmaxf(var, 0.f));
        float inv = 1.f / (sd + 1e-8f);
        for (int i = tid; i < L; i += 256) srow[off + i] = (p[i] - m) * inv;
        off += L;
    }
    __syncthreads();

    float n2 = 0.f;
    for (int i = tid; i < D; i += 256) { float v = srow[i]; n2 += v * v; }
    n2 = blockSum(n2, sbuf);
    float n  = fmaxf(sqrtf(n2), NORM_EPS);
    float t  = tanhf(n);
    float sc = t / n;
    for (int i = tid; i < D; i += 256)
        xout[(size_t)row * D + i] = srow[i] * sc;
    if (tid == 0) nout[row] = t;
}

/* ------------------------------------------------------------------ */
/* SGEMM: C[M,N] = A[M,K] * W[K,N], fp32.                              */
/* 128x128x16 tiles, 8x8 microtiles, 256 threads, double-buffered:     */
/* prefetch next K-tile into registers while computing current tile.   */
/* ------------------------------------------------------------------ */
__global__ __launch_bounds__(256) void sgemm_kernel(
    const float* __restrict__ A, const float* __restrict__ W,
    float* __restrict__ C, int M, int N, int K)
{
    __shared__ float As[2][16][132];   /* +4 pad */
    __shared__ float Bs[2][16][128];

    const int tid = threadIdx.x;
    const int tx = tid & 15, ty = tid >> 4;
    const int m0 = blockIdx.y << 7, n0 = blockIdx.x << 7;

    float acc[8][8];
    #pragma unroll
    for (int i = 0; i < 8; i++)
        #pragma unroll
        for (int j = 0; j < 8; j++) acc[i][j] = 0.f;

    const int  ktiles = (K + 15) >> 4;
    const bool nvec   = ((N & 3) == 0);

    /* per-thread load coordinates (fixed across tiles) */
    const int ar[8] = { (tid + 0*256) >> 4, (tid + 1*256) >> 4, (tid + 2*256) >> 4, (tid + 3*256) >> 4,
                        (tid + 4*256) >> 4, (tid + 5*256) >> 4, (tid + 6*256) >> 4, (tid + 7*256) >> 4 };
    const int ac = tid & 15;  /* same low bits for every chunk since stride 256 */

    float  ra_pf[8];
    float4 rb_pf[2];

    /* ---- helpers as lambdas ---- */
    auto loadA_regs = [&](int k0) {
        #pragma unroll
        for (int i = 0; i < 8; i++) {
            int gm = m0 + ar[i], gk = k0 + ac;
            ra_pf[i] = (gm < M && gk < K) ? __ldg(&A[(size_t)gm * K + gk]) : 0.f;
        }
    };
    auto loadB_regs = [&](int k0) {
        #pragma unroll
        for (int i = 0; i < 2; i++) {
            int e = (tid + (i << 8)) << 2;
            int r = e >> 7, c = e & 127;
            int gk = k0 + r, gn = n0 + c;
            float4 v = make_float4(0.f, 0.f, 0.f, 0.f);
            if (gk < K) {
                if (nvec && gn + 3 < N) {
                    v = __ldg(reinterpret_cast<const float4*>(&W[(size_t)gk * N + gn]));
                } else {
                    if (gn     < N) v.x = W[(size_t)gk * N + gn];
                    if (gn + 1 < N) v.y = W[(size_t)gk * N + gn + 1];
                    if (gn + 2 < N) v.z = W[(size_t)gk * N + gn + 2];
                    if (gn + 3 < N) v.w = W[(size_t)gk * N + gn + 3];
                }
            }
            rb_pf[i] = v;
        }
    };
    auto store_smem = [&](int buf) {
        #pragma unroll
        for (int i = 0; i < 8; i++) As[buf][ac][ar[i]] = ra_pf[i];
        #pragma unroll
        for (int i = 0; i < 2; i++) {
            int e = (tid + (i << 8)) << 2;
            int r = e >> 7, c = e & 127;
            *reinterpret_cast<float4*>(&Bs[buf][r][c]) = rb_pf[i];
        }
    };

    /* prologue: tile 0 -> buffer 0 */
    loadA_regs(0);
    loadB_regs(0);
    store_smem(0);
    __syncthreads();

    for (int kt = 0; kt < ktiles; ++kt) {
        const int cur = kt & 1;

        if (kt + 1 < ktiles) {          /* prefetch next tile into registers */
            loadA_regs((kt + 1) << 4);
            loadB_regs((kt + 1) << 4);
        }

        #pragma unroll
        for (int k = 0; k < 16; k++) {
            float ra[8], rb[8];
            *reinterpret_cast<float4*>(&ra[0]) = *reinterpret_cast<float4*>(&As[cur][k][ty * 8]);
            *reinterpret_cast<float4*>(&ra[4]) = *reinterpret_cast<float4*>(&As[cur][k][ty * 8 + 4]);
            *reinterpret_cast<float4*>(&rb[0]) = *reinterpret_cast<float4*>(&Bs[cur][k][tx * 4]);
            *reinterpret_cast<float4*>(&rb[4]) = *reinterpret_cast<float4*>(&Bs[cur][k][64 + tx * 4]);
            #pragma unroll
            for (int i = 0; i < 8; i++)
                #pragma unroll
                for (int j = 0; j < 8; j++)
                    acc[i][j] += ra[i] * rb[j];
        }

        if (kt + 1 < ktiles) {
            store_smem(cur ^ 1);
            __syncthreads();
        }
    }

    #pragma unroll
    for (int i = 0; i < 8; i++) {
        int gm = m0 + ty * 8 + i;
        if (gm >= M) continue;
        #pragma unroll
        for (int j = 0; j < 8; j++) {
            int gn = n0 + ((j < 4) ? (tx * 4 + j) : (64 + tx * 4 + (j - 4)));
            if (gn < N) C[(size_t)gm * N + gn] = acc[i][j];
        }
    }
}

/* ------------------------------------------------------------------ */
/* Hyperbolic epilogue: given mx = x@W and xn = ||x|| (carried),       */
/*   y   = projx( mobius_matvec finalize )                             */
/*   z   = projx( mobius_add(y, b) )                                   */
/*   out = do_tanh ? projx(expmap0(tanh(logmap0(z)))) : z              */
/* Stores out and its analytic norm. One block per row, D <= 1024.     */
/* ------------------------------------------------------------------ */
__global__ __launch_bounds__(256) void epi_kernel(
    const float* __restrict__ mx, const float* __restrict__ xn_in,
    const float* __restrict__ bv,
    float* __restrict__ out, float* __restrict__ nout,
    int D, int do_tanh)
{
    __shared__ float sbuf[8];
    const int row = blockIdx.x, tid = threadIdx.x;

    float vv[4], vb[4];
    float mx2 = 0.f, mxb = 0.f, b2 = 0.f;
    #pragma unroll
    for (int q = 0; q < 4; q++) {
        int i = tid + (q << 8);
        float v = 0.f, bb = 0.f;
        if (i < D) { v = mx[(size_t)row * D + i]; bb = bv[i]; }
        vv[q] = v; vb[q] = bb;
        mx2 += v * v; mxb += v * bb; b2 += bb * bb;
    }
    mx2 = blockSum(mx2, sbuf);
    mxb = blockSum(mxb, sbuf);
    b2  = blockSum(b2,  sbuf);

    /* mobius_matvec finalize + projx */
    float mxn = fmaxf(sqrtf(mx2), NORM_EPS);
    float xn  = fmaxf(xn_in[row], NORM_EPS);
    float art = atanhf(fminf(xn, ART_CLIP));
    float s1  = tanhf((mxn / xn) * art) / mxn;
    float yn  = s1 * mxn;
    if (yn > MAXNORM) { s1 *= MAXNORM / yn; yn = MAXNORM; }

    /* mobius_add(y, b) */
    float y2    = yn * yn;
    float xy    = s1 * mxb;
    float alpha = 1.f + 2.f * xy + b2;
    float beta  = 1.f - y2;
    float den   = fmaxf(1.f + 2.f * xy + y2 * b2, NORM_EPS);
    float ca = alpha * s1 / den, cb = beta / den;

    float z[4];
    float z2 = 0.f;
    #pragma unroll
    for (int q = 0; q < 4; q++) { z[q] = ca * vv[q] + cb * vb[q]; z2 += z[q] * z[q]; }
    z2 = blockSum(z2, sbuf);
    float zn = sqrtf(z2);
    float ps = (zn > MAXNORM) ? (MAXNORM / zn) : 1.f;
    float hn = zn * ps;

    if (!do_tanh) {
        #pragma unroll
        for (int q = 0; q < 4; q++) {
            int i = tid + (q << 8);
            if (i < D) out[(size_t)row * D + i] = z[q] * ps;
        }
        if (tid == 0) nout[row] = hn;
        return;
    }

    /* mobius_tanh: logmap0 -> tanh -> expmap0 -> projx */
    float n1 = fmaxf(hn, NORM_EPS);
    float ls = atanhf(fminf(n1, ART_CLIP)) / n1 * ps;
    float tq[4];
    float t2 = 0.f;
    #pragma unroll
    for (int q = 0; q < 4; q++) { tq[q] = tanhf(ls * z[q]); t2 += tq[q] * tq[q]; }
    t2 = blockSum(t2, sbuf);
    float n2n = fmaxf(sqrtf(t2), NORM_EPS);
    float on  = tanhf(n2n);
    float es  = on / n2n;
    if (on > MAXNORM) { es *= MAXNORM / on; on = MAXNORM; }
    #pragma unroll
    for (int q = 0; q < 4; q++) {
        int i = tid + (q << 8);
        if (i < D) out[(size_t)row * D + i] = es * tq[q];
    }
    if (tid == 0) nout[row] = on;
}

/* ------------------------------------------------------------------ */
/* mid = projx( mobius_add( 0.27 (x) head, 0.73 (x) tail ) ), D=256    */
/* ------------------------------------------------------------------ */
__global__ __launch_bounds__(256) void mid_kernel(
    const float* __restrict__ head, const float* __restrict__ hn_in,
    const float* __restrict__ tail, const float* __restrict__ tn_in,
    float* __restrict__ mid, float* __restrict__ nout)
{
    __shared__ float sbuf[8];
    const int row = blockIdx.x, tid = threadIdx.x;

    float h = head[(size_t)row * HDIM + tid];
    float t = tail[(size_t)row * HDIM + tid];
    float hn = fmaxf(hn_in[row], NORM_EPS);
    float tn = fmaxf(tn_in[row], NORM_EPS);
    float na = tanhf(0.27f * atanhf(fminf(hn, ART_CLIP)));
    float nc = tanhf(0.73f * atanhf(fminf(tn, ART_CLIP)));
    float a = (na / hn) * h;
    float c = (nc / tn) * t;

    float dot = blockSum(a * c, sbuf);
    float a2 = na * na, c2 = nc * nc;
    float alpha = 1.f + 2.f * dot + c2;
    float beta  = 1.f - a2;
    float den   = fmaxf(1.f + 2.f * dot + a2 * c2, NORM_EPS);
    float z = (alpha * a + beta * c) / den;

    float z2 = blockSum(z * z, sbuf);
    float zn = sqrtf(z2);
    float ps = (zn > MAXNORM) ? (MAXNORM / zn) : 1.f;
    mid[(size_t)row * HDIM + tid] = z * ps;
    if (tid == 0) nout[row] = zn * ps;
}

/* ------------------------------------------------------------------ */
/* Launch                                                              */
/* ------------------------------------------------------------------ */
static inline dim3 gemm_grid(int M, int N)
{
    return dim3((unsigned)((N + 127) / 128), (unsigned)((M + 127) / 128));
}

extern "C" void kernel_launch(void* const* d_in, const int* in_sizes, int n_in,
                              void* d_out, int out_size)
{
    const float* chem = (const float*)d_in[0];
    const float* dpc  = (const float*)d_in[1];
    const float* macc = (const float*)d_in[2];
    const float* ecfp = (const float*)d_in[3];
    const float* esm  = (const float*)d_in[4];
    const float* tpc  = (const float*)d_in[5];
    const float* mer  = (const float*)d_in[6];
    const float* Wd1 = (const float*)d_in[7];  const float* bd1 = (const float*)d_in[8];
    const float* Wd2 = (const float*)d_in[9];  const float* bd2 = (const float*)d_in[10];
    const float* Wd3 = (const float*)d_in[11]; const float* bd3 = (const float*)d_in[12];
    const float* Wt1 = (const float*)d_in[13]; const float* bt1 = (const float*)d_in[14];
    const float* Wt2 = (const float*)d_in[15]; const float* bt2 = (const float*)d_in[16];
    const float* Wt3 = (const float*)d_in[17]; const float* bt3 = (const float*)d_in[18];
    const float* Wm1 = (const float*)d_in[19]; const float* bm1 = (const float*)d_in[20];
    const float* Wm2 = (const float*)d_in[21]; const float* bm2 = (const float*)d_in[22];
    const float* Wm3 = (const float*)d_in[23]; const float* bm3 = (const float*)d_in[24];
    float* outp = (float*)d_out;

    int B = in_sizes[0] / 768;
    if (B > MAXB) B = MAXB;

    float *xd, *xt, *mx, *ha, *hb, *head, *tail, *mid, *r1, *r2;
    float *na, *nb, *nhead, *ntail, *nmid;
    cudaGetSymbolAddress((void**)&xd,   g_xd);
    cudaGetSymbolAddress((void**)&xt,   g_xt);
    cudaGetSymbolAddress((void**)&mx,   g_mx);
    cudaGetSymbolAddress((void**)&ha,   g_ha);
    cudaGetSymbolAddress((void**)&hb,   g_hb);
    cudaGetSymbolAddress((void**)&head, g_head);
    cudaGetSymbolAddress((void**)&tail, g_tail);
    cudaGetSymbolAddress((void**)&mid,  g_mid);
    cudaGetSymbolAddress((void**)&r1,   g_r1);
    cudaGetSymbolAddress((void**)&r2,   g_r2);
    cudaGetSymbolAddress((void**)&na,   g_na);
    cudaGetSymbolAddress((void**)&nb,   g_nb);
    cudaGetSymbolAddress((void**)&nhead, g_nhead);
    cudaGetSymbolAddress((void**)&ntail, g_ntail);
    cudaGetSymbolAddress((void**)&nmid,  g_nmid);

    const int D = 1711;

    /* ---- prep ---- */
    prep_kernel<<<B, 256>>>(chem, dpc, macc, ecfp, 768, 11, 167, 765, 4, D, xd, na);
    prep_kernel<<<B, 256>>>(esm,  tpc, mer,  mer,  1280, 11, 420, 0, 3, D, xt, nb);

    /* ---- drug tower (input norm in na) ---- */
    sgemm_kernel<<<gemm_grid(B, 1024), 256>>>(xd, Wd1, mx, B, 1024, D);
    epi_kernel<<<B, 256>>>(mx, na, bd1, ha, nhead /*tmp*/, 1024, 1);
    sgemm_kernel<<<gemm_grid(B, 512), 256>>>(ha, Wd2, mx, B, 512, 1024);
    epi_kernel<<<B, 256>>>(mx, nhead, bd2, hb, na, 512, 1);
    sgemm_kernel<<<gemm_grid(B, 256), 256>>>(hb, Wd3, mx, B, 256, 512);
    epi_kernel<<<B, 256>>>(mx, na, bd3, head, nhead, 256, 0);

    /* ---- target tower (input norm in nb) ---- */
    sgemm_kernel<<<gemm_grid(B, 1024), 256>>>(xt, Wt1, mx, B, 1024, D);
    epi_kernel<<<B, 256>>>(mx, nb, bt1, ha, ntail /*tmp*/, 1024, 1);
    sgemm_kernel<<<gemm_grid(B, 512), 256>>>(ha, Wt2, mx, B, 512, 1024);
    epi_kernel<<<B, 256>>>(mx, ntail, bt2, hb, nb, 512, 1);
    sgemm_kernel<<<gemm_grid(B, 256), 256>>>(hb, Wt3, mx, B, 256, 512);
    epi_kernel<<<B, 256>>>(mx, nb, bt3, tail, ntail, 256, 0);

    /* ---- midpoint ---- */
    mid_kernel<<<B, 256>>>(head, nhead, tail, ntail, mid, nmid);

    /* ---- mixer ---- */
    sgemm_kernel<<<gemm_grid(B, 64), 256>>>(mid, Wm1, mx, B, 64, 256);
    epi_kernel<<<B, 256>>>(mx, nmid, bm1, r1, na, 64, 1);
    sgemm_kernel<<<gemm_grid(B, 32), 256>>>(r1, Wm2, mx, B, 32, 64);
    epi_kernel<<<B, 256>>>(mx, na, bm2, r2, nb, 32, 1);
    sgemm_kernel<<<gemm_grid(B, 2), 256>>>(r2, Wm3, mx, B, 2, 32);
    epi_kernel<<<B, 256>>>(mx, nb, bm3, outp, na, 2, 0);
}

// round 7
// speedup vs baseline: 2.2427x; 2.2427x over previous
#include <cuda_runtime.h>
#include <cuda_bf16.h>
#include <cstdint>

#define MAXB     16384
#define HDIM     256
#define MAXNORM  0.996f           /* (1 - 4e-3)/sqrt(c), c=1 */
#define ART_CLIP (1.0f - 1e-5f)   /* artanh clip */
#define NORM_EPS 1e-15f
#define KP1      1728             /* K=1711 padded to multiple of 64 */

/* ------------------------------------------------------------------ */
/* Scratch (device globals; no allocation allowed)                     */
/* ------------------------------------------------------------------ */
__device__ __align__(16) __nv_bfloat16 g_xh [MAXB * KP1];
__device__ __align__(16) __nv_bfloat16 g_xl [MAXB * KP1];
__device__ __align__(16) __nv_bfloat16 g_ah [MAXB * 1024];
__device__ __align__(16) __nv_bfloat16 g_al [MAXB * 1024];
__device__ __align__(16) __nv_bfloat16 g_bh [MAXB * 512];
__device__ __align__(16) __nv_bfloat16 g_bl [MAXB * 512];
__device__ __align__(16) __nv_bfloat16 g_w1h[1024 * KP1];
__device__ __align__(16) __nv_bfloat16 g_w1l[1024 * KP1];
__device__ __align__(16) __nv_bfloat16 g_w2h[512 * 1024];
__device__ __align__(16) __nv_bfloat16 g_w2l[512 * 1024];
__device__ __align__(16) __nv_bfloat16 g_w3h[256 * 512];
__device__ __align__(16) __nv_bfloat16 g_w3l[256 * 512];

__device__ float g_mx  [MAXB * 1024];
__device__ float g_head[MAXB * HDIM];
__device__ float g_tail[MAXB * HDIM];
__device__ float g_mid [MAXB * HDIM];
__device__ float g_r1  [MAXB * 64];
__device__ float g_r2  [MAXB * 32];
__device__ float g_na  [MAXB];
__device__ float g_nb  [MAXB];
__device__ float g_nhead[MAXB];
__device__ float g_ntail[MAXB];
__device__ float g_nmid [MAXB];

/* ------------------------------------------------------------------ */
/* PTX helpers (family-portable only: ldmatrix / mma.sync / cp.async)  */
/* ------------------------------------------------------------------ */
__device__ __forceinline__ uint32_t smem_u32(const void* p) {
    uint32_t a;
    asm("{ .reg .u64 t; cvta.to.shared.u64 t, %1; cvt.u32.u64 %0, t; }" : "=r"(a) : "l"(p));
    return a;
}
#define CP_ASYNC(dst, src) \
    asm volatile("cp.async.cg.shared.global [%0], [%1], 16;" :: "r"(dst), "l"(src) : "memory")
#define CP_COMMIT() asm volatile("cp.async.commit_group;" ::: "memory")
#define CP_WAIT1()  asm volatile("cp.async.wait_group 1;" ::: "memory")
#define CP_WAIT0()  asm volatile("cp.async.wait_group 0;" ::: "memory")

__device__ __forceinline__ void ldm4(uint32_t r[4], uint32_t addr) {
    asm volatile("ldmatrix.sync.aligned.m8n8.x4.shared.b16 {%0,%1,%2,%3}, [%4];"
        : "=r"(r[0]), "=r"(r[1]), "=r"(r[2]), "=r"(r[3]) : "r"(addr) : "memory");
}
__device__ __forceinline__ void mma16816(float c[4], const uint32_t a[4],
                                         uint32_t b0, uint32_t b1) {
    asm volatile(
        "mma.sync.aligned.m16n8k16.row.col.f32.bf16.bf16.f32 "
        "{%0,%1,%2,%3}, {%4,%5,%6,%7}, {%8,%9}, {%0,%1,%2,%3};"
        : "+f"(c[0]), "+f"(c[1]), "+f"(c[2]), "+f"(c[3])
        : "r"(a[0]), "r"(a[1]), "r"(a[2]), "r"(a[3]), "r"(b0), "r"(b1));
}
#define SWZ(off) ((off) ^ (((off) >> 3) & 0x70))

/* hgemm smem: 4 tiles (Ah,Al,Bh,Bl) of 128x64 bf16 = 16KB, x2 stages */
#define HT_TILE  16384
#define HT_STAGE (4 * HT_TILE)
#define HT_SMEM  (2 * HT_STAGE + 1024)

/* ------------------------------------------------------------------ */
/* math helpers                                                        */
/* ------------------------------------------------------------------ */
__device__ __forceinline__ float blockSum(float v, float* sbuf)
{
    #pragma unroll
    for (int o = 16; o > 0; o >>= 1)
        v += __shfl_xor_sync(0xffffffffu, v, o);
    int w = threadIdx.x >> 5;
    if ((threadIdx.x & 31) == 0) sbuf[w] = v;
    __syncthreads();
    float r = ((sbuf[0] + sbuf[1]) + (sbuf[2] + sbuf[3]))
            + ((sbuf[4] + sbuf[5]) + (sbuf[6] + sbuf[7]));
    __syncthreads();
    return r;
}

__device__ __forceinline__ float fast_tanhf(float x)
{
    float ax = fabsf(x);
    float e  = __expf(2.f * ax);
    float t  = 1.f - __fdividef(2.f, e + 1.f);
    float x2 = x * x;
    float tp = x * (1.f + x2 * (-0.33333333f + 0.13333333f * x2));
    float ts = copysignf(t, x);
    return (ax < 0.04f) ? tp : ts;
}

__device__ __forceinline__ void bsplit(float v, __nv_bfloat16* ph, __nv_bfloat16* pl)
{
    __nv_bfloat16 h = __float2bfloat16(v);
    *ph = h;
    *pl = __float2bfloat16(v - __bfloat162float(h));
}

/* ------------------------------------------------------------------ */
/* Prep: segment zscore (ddof=1) -> concat -> expmap0 -> bf16 hi/lo    */
/* ------------------------------------------------------------------ */
__global__ __launch_bounds__(256) void prep_kernel(
    const float* __restrict__ s0, const float* __restrict__ s1,
    const float* __restrict__ s2, const float* __restrict__ s3,
    int l0, int l1, int l2, int l3, int nseg, int D,
    __nv_bfloat16* __restrict__ xh, __nv_bfloat16* __restrict__ xl,
    float* __restrict__ nout)
{
    __shared__ float srow[1712];
    __shared__ float sbuf[8];
    const int row = blockIdx.x, tid = threadIdx.x;
    const float* sp[4] = { s0, s1, s2, s3 };
    int          ln[4] = { l0, l1, l2, l3 };

    int off = 0;
    for (int sg = 0; sg < nseg; ++sg) {
        int L = ln[sg];
        const float* p = sp[sg] + (size_t)row * L;
        float s = 0.f, ss = 0.f;
        for (int i = tid; i < L; i += 256) { float v = p[i]; s += v; ss += v * v; }
        s  = blockSum(s,  sbuf);
        ss = blockSum(ss, sbuf);
        float m   = s / (float)L;
        float var = (ss - s * m) / (float)(L - 1);
        float sd  = sqrtf(fmaxf(var, 0.f));
        float inv = 1.f / (sd + 1e-8f);
        for (int i = tid; i < L; i += 256) srow[off + i] = (p[i] - m) * inv;
        off += L;
    }
    __syncthreads();

    float n2 = 0.f;
    for (int i = tid; i < D; i += 256) { float v = srow[i]; n2 += v * v; }
    n2 = blockSum(n2, sbuf);
    float n  = fmaxf(sqrtf(n2), NORM_EPS);
    float t  = tanhf(n);
    float sc = t / n;
    for (int i = tid; i < KP1; i += 256) {
        float v = (i < D) ? srow[i] * sc : 0.f;
        bsplit(v, &xh[(size_t)row * KP1 + i], &xl[(size_t)row * KP1 + i]);
    }
    if (tid == 0) nout[row] = t;
}

/* ------------------------------------------------------------------ */
/* Weight transpose + split: W[K,N] fp32 -> WT_hi/lo [N,KPd] bf16      */
/* ------------------------------------------------------------------ */
__global__ void wsplit_kernel(const float* __restrict__ W, int K, int N, int KPd,
                              __nv_bfloat16* __restrict__ th,
                              __nv_bfloat16* __restrict__ tl)
{
    __shared__ float tile[32][33];
    const int k0 = blockIdx.x << 5, n0 = blockIdx.y << 5;
    const int tx = threadIdx.x, ty = threadIdx.y;   /* 32 x 8 */
    #pragma unroll
    for (int s = 0; s < 4; ++s) {
        int k = k0 + ty + (s << 3);
        tile[ty + (s << 3)][tx] = (k < K && n0 + tx < N) ? W[(size_t)k * N + n0 + tx] : 0.f;
    }
    __syncthreads();
    #pragma unroll
    for (int s = 0; s < 4; ++s) {
        int n = n0 + ty + (s << 3);
        int k = k0 + tx;
        if (n < N && k < KPd)
            bsplit(tile[tx][ty + (s << 3)],
                   &th[(size_t)n * KPd + k], &tl[(size_t)n * KPd + k]);
    }
}

/* ------------------------------------------------------------------ */
/* HMMA GEMM: C[M,N] = A[M,K] * B[N,K]^T via mma.sync bf16 3-term      */
/* split. 128x128 CTA tile, 8 warps (2m x 4n) of 64x32, K-chunks 64,   */
/* cp.async double buffer. Requires M%128==0, N%128==0, K%64==0.       */
/* ------------------------------------------------------------------ */
__global__ __launch_bounds__(256) void hgemm_kernel(
    const __nv_bfloat16* __restrict__ Ah, const __nv_bfloat16* __restrict__ Al, int sA,
    const __nv_bfloat16* __restrict__ Bh, const __nv_bfloat16* __restrict__ Bl, int sB,
    float* __restrict__ C, int N, int K)
{
    extern __shared__ char smem[];
    const uint32_t tb = (smem_u32(smem) + 1023u) & ~1023u;

    const int tid  = threadIdx.x;
    const int lane = tid & 31, warp = tid >> 5;
    const int wm = warp >> 2, wn = warp & 3;
    const int m0 = blockIdx.y << 7, n0 = blockIdx.x << 7;

    /* global load mapping: j = 16B unit in row (8), r0 = row group */
    const int j = tid & 7, r0 = tid >> 3;
    const __nv_bfloat16* gp[4] = {
        Ah + (size_t)m0 * sA, Al + (size_t)m0 * sA,
        Bh + (size_t)n0 * sB, Bl + (size_t)n0 * sB };
    const int st[4] = { sA, sA, sB, sB };

    auto load_chunk = [&](int c, int s) {
        uint32_t base = tb + s * HT_STAGE;
        #pragma unroll
        for (int t = 0; t < 4; ++t) {
            const __nv_bfloat16* p = gp[t] + (size_t)c * 64 + j * 8;
            #pragma unroll
            for (int ps = 0; ps < 4; ++ps) {
                int r = r0 + (ps << 5);
                CP_ASYNC(base + t * HT_TILE + SWZ(r * 128 + j * 16),
                         p + (size_t)r * st[t]);
            }
        }
        CP_COMMIT();
    };

    /* ldmatrix offsets within a stage (lane-dependent, chunk-invariant) */
    uint32_t aoff[4][4], boff[4][2];
    {
        const int arow  = wm * 64 + (lane & 15);
        const int abyte = (lane >> 4) * 16;
        const int brow  = wn * 32 + ((lane >> 4) << 3) + (lane & 7);
        const int bbyte = ((lane >> 3) & 1) * 16;
        #pragma unroll
        for (int ks = 0; ks < 4; ++ks) {
            #pragma unroll
            for (int im = 0; im < 4; ++im)
                aoff[ks][im] = SWZ((arow + im * 16) * 128 + ks * 32 + abyte);
            #pragma unroll
            for (int inp = 0; inp < 2; ++inp)
                boff[ks][inp] = SWZ((brow + inp * 16) * 128 + ks * 32 + bbyte);
        }
    }

    float acc[4][4][4];
    #pragma unroll
    for (int i = 0; i < 4; ++i)
        #pragma unroll
        for (int jn = 0; jn < 4; ++jn)
            #pragma unroll
            for (int q = 0; q < 4; ++q) acc[i][jn][q] = 0.f;

    const int nch = K >> 6;
    load_chunk(0, 0);

    for (int c = 0; c < nch; ++c) {
        if (c + 1 < nch) { load_chunk(c + 1, (c + 1) & 1); CP_WAIT1(); }
        else             { CP_WAIT0(); }
        __syncthreads();

        const uint32_t sb = tb + (c & 1) * HT_STAGE;
        #pragma unroll
        for (int ks = 0; ks < 4; ++ks) {
            uint32_t ah[4][4], alr[4][4];
            #pragma unroll
            for (int im = 0; im < 4; ++im) {
                ldm4(ah[im],  sb + aoff[ks][im]);
                ldm4(alr[im], sb + HT_TILE + aoff[ks][im]);
            }
            #pragma unroll
            for (int inp = 0; inp < 2; ++inp) {
                uint32_t bhr[4], blr[4];
                ldm4(bhr, sb + 2 * HT_TILE + boff[ks][inp]);
                ldm4(blr, sb + 3 * HT_TILE + boff[ks][inp]);
                #pragma unroll
                for (int im = 0; im < 4; ++im) {
                    mma16816(acc[im][2 * inp],     ah[im],  bhr[0], bhr[1]);
                    mma16816(acc[im][2 * inp + 1], ah[im],  bhr[2], bhr[3]);
                    mma16816(acc[im][2 * inp],     ah[im],  blr[0], blr[1]);
                    mma16816(acc[im][2 * inp + 1], ah[im],  blr[2], blr[3]);
                    mma16816(acc[im][2 * inp],     alr[im], bhr[0], bhr[1]);
                    mma16816(acc[im][2 * inp + 1], alr[im], bhr[2], bhr[3]);
                }
            }
        }
        __syncthreads();
    }

    /* store C */
    const int g = lane >> 2, q = lane & 3;
    #pragma unroll
    for (int im = 0; im < 4; ++im) {
        #pragma unroll
        for (int in = 0; in < 4; ++in) {
            float* p0 = C + (size_t)(m0 + wm * 64 + im * 16 + g) * N
                          + n0 + wn * 32 + in * 8 + q * 2;
            *reinterpret_cast<float2*>(p0) =
                make_float2(acc[im][in][0], acc[im][in][1]);
            *reinterpret_cast<float2*>(p0 + (size_t)8 * N) =
                make_float2(acc[im][in][2], acc[im][in][3]);
        }
    }
}

/* ------------------------------------------------------------------ */
/* fp32 SGEMM (mixer only), double-buffered 128x128x16                 */
/* ------------------------------------------------------------------ */
__global__ __launch_bounds__(256) void sgemm_kernel(
    const float* __restrict__ A, const float* __restrict__ W,
    float* __restrict__ C, int M, int N, int K)
{
    __shared__ float As[2][16][132];
    __shared__ float Bs[2][16][128];

    const int tid = threadIdx.x;
    const int tx = tid & 15, ty = tid >> 4;
    const int m0 = blockIdx.y << 7, n0 = blockIdx.x << 7;

    float acc[8][8];
    #pragma unroll
    for (int i = 0; i < 8; i++)
        #pragma unroll
        for (int jj = 0; jj < 8; jj++) acc[i][jj] = 0.f;

    const int  ktiles = (K + 15) >> 4;
    const bool nvec   = ((N & 3) == 0);

    const int ar[8] = { (tid + 0*256) >> 4, (tid + 1*256) >> 4, (tid + 2*256) >> 4, (tid + 3*256) >> 4,
                        (tid + 4*256) >> 4, (tid + 5*256) >> 4, (tid + 6*256) >> 4, (tid + 7*256) >> 4 };
    const int ac = tid & 15;

    float  ra_pf[8];
    float4 rb_pf[2];

    auto loadA = [&](int k0) {
        #pragma unroll
        for (int i = 0; i < 8; i++) {
            int gm = m0 + ar[i], gk = k0 + ac;
            ra_pf[i] = (gm < M && gk < K) ? __ldg(&A[(size_t)gm * K + gk]) : 0.f;
        }
    };
    auto loadB = [&](int k0) {
        #pragma unroll
        for (int i = 0; i < 2; i++) {
            int e = (tid + (i << 8)) << 2;
            int r = e >> 7, c = e & 127;
            int gk = k0 + r, gn = n0 + c;
            float4 v = make_float4(0.f, 0.f, 0.f, 0.f);
            if (gk < K) {
                if (nvec && gn + 3 < N) {
                    v = __ldg(reinterpret_cast<const float4*>(&W[(size_t)gk * N + gn]));
                } else {
                    if (gn     < N) v.x = W[(size_t)gk * N + gn];
                    if (gn + 1 < N) v.y = W[(size_t)gk * N + gn + 1];
                    if (gn + 2 < N) v.z = W[(size_t)gk * N + gn + 2];
                    if (gn + 3 < N) v.w = W[(size_t)gk * N + gn + 3];
                }
            }
            rb_pf[i] = v;
        }
    };
    auto store = [&](int buf) {
        #pragma unroll
        for (int i = 0; i < 8; i++) As[buf][ac][ar[i]] = ra_pf[i];
        #pragma unroll
        for (int i = 0; i < 2; i++) {
            int e = (tid + (i << 8)) << 2;
            int r = e >> 7, c = e & 127;
            *reinterpret_cast<float4*>(&Bs[buf][r][c]) = rb_pf[i];
        }
    };

    loadA(0); loadB(0); store(0);
    __syncthreads();

    for (int kt = 0; kt < ktiles; ++kt) {
        const int cur = kt & 1;
        if (kt + 1 < ktiles) { loadA((kt + 1) << 4); loadB((kt + 1) << 4); }

        #pragma unroll
        for (int k = 0; k < 16; k++) {
            float ra[8], rb[8];
            *reinterpret_cast<float4*>(&ra[0]) = *reinterpret_cast<float4*>(&As[cur][k][ty * 8]);
            *reinterpret_cast<float4*>(&ra[4]) = *reinterpret_cast<float4*>(&As[cur][k][ty * 8 + 4]);
            *reinterpret_cast<float4*>(&rb[0]) = *reinterpret_cast<float4*>(&Bs[cur][k][tx * 4]);
            *reinterpret_cast<float4*>(&rb[4]) = *reinterpret_cast<float4*>(&Bs[cur][k][64 + tx * 4]);
            #pragma unroll
            for (int i = 0; i < 8; i++)
                #pragma unroll
                for (int jj = 0; jj < 8; jj++)
                    acc[i][jj] += ra[i] * rb[jj];
        }

        if (kt + 1 < ktiles) { store(cur ^ 1); __syncthreads(); }
    }

    #pragma unroll
    for (int i = 0; i < 8; i++) {
        int gm = m0 + ty * 8 + i;
        if (gm >= M) continue;
        #pragma unroll
        for (int jj = 0; jj < 8; jj++) {
            int gn = n0 + ((jj < 4) ? (tx * 4 + jj) : (64 + tx * 4 + (jj - 4)));
            if (gn < N) C[(size_t)gm * N + gn] = acc[i][jj];
        }
    }
}

/* ------------------------------------------------------------------ */
/* Hyperbolic epilogue. Outputs fp32 OR bf16 hi/lo (next GEMM input).  */
/* ------------------------------------------------------------------ */
__global__ __launch_bounds__(256) void epi_kernel(
    const float* __restrict__ mx, const float* __restrict__ xn_in,
    const float* __restrict__ bv,
    float* __restrict__ out,
    __nv_bfloat16* __restrict__ oh, __nv_bfloat16* __restrict__ ol,
    float* __restrict__ nout,
    int D, int do_tanh, int bf16out)
{
    __shared__ float sbuf[8];
    const int row = blockIdx.x, tid = threadIdx.x;

    float vv[4], vb[4];
    float mx2 = 0.f, mxb = 0.f, b2 = 0.f;
    #pragma unroll
    for (int q = 0; q < 4; q++) {
        int i = tid + (q << 8);
        float v = 0.f, bb = 0.f;
        if (i < D) { v = mx[(size_t)row * D + i]; bb = bv[i]; }
        vv[q] = v; vb[q] = bb;
        mx2 += v * v; mxb += v * bb; b2 += bb * bb;
    }
    mx2 = blockSum(mx2, sbuf);
    mxb = blockSum(mxb, sbuf);
    b2  = blockSum(b2,  sbuf);

    float mxn = fmaxf(sqrtf(mx2), NORM_EPS);
    float xn  = fmaxf(xn_in[row], NORM_EPS);
    float art = atanhf(fminf(xn, ART_CLIP));
    float s1  = tanhf((mxn / xn) * art) / mxn;
    float yn  = s1 * mxn;
    if (yn > MAXNORM) { s1 *= MAXNORM / yn; yn = MAXNORM; }

    float y2    = yn * yn;
    float xy    = s1 * mxb;
    float alpha = 1.f + 2.f * xy + b2;
    float beta  = 1.f - y2;
    float den   = fmaxf(1.f + 2.f * xy + y2 * b2, NORM_EPS);
    float ca = alpha * s1 / den, cb = beta / den;

    float z[4];
    float z2 = 0.f;
    #pragma unroll
    for (int q = 0; q < 4; q++) { z[q] = ca * vv[q] + cb * vb[q]; z2 += z[q] * z[q]; }
    z2 = blockSum(z2, sbuf);
    float zn = sqrtf(z2);
    float ps = (zn > MAXNORM) ? (MAXNORM / zn) : 1.f;
    float hn = zn * ps;

    if (!do_tanh) {
        #pragma unroll
        for (int q = 0; q < 4; q++) {
            int i = tid + (q << 8);
            if (i < D) {
                float v = z[q] * ps;
                if (bf16out) bsplit(v, &oh[(size_t)row * D + i], &ol[(size_t)row * D + i]);
                else         out[(size_t)row * D + i] = v;
            }
        }
        if (tid == 0) nout[row] = hn;
        return;
    }

    float n1 = fmaxf(hn, NORM_EPS);
    float ls = atanhf(fminf(n1, ART_CLIP)) / n1 * ps;
    float tq[4];
    float t2 = 0.f;
    #pragma unroll
    for (int q = 0; q < 4; q++) { tq[q] = fast_tanhf(ls * z[q]); t2 += tq[q] * tq[q]; }
    t2 = blockSum(t2, sbuf);
    float n2n = fmaxf(sqrtf(t2), NORM_EPS);
    float on  = tanhf(n2n);
    float es  = on / n2n;
    if (on > MAXNORM) { es *= MAXNORM / on; on = MAXNORM; }
    #pragma unroll
    for (int q = 0; q < 4; q++) {
        int i = tid + (q << 8);
        if (i < D) {
            float v = es * tq[q];
            if (bf16out) bsplit(v, &oh[(size_t)row * D + i], &ol[(size_t)row * D + i]);
            else         out[(size_t)row * D + i] = v;
        }
    }
    if (tid == 0) nout[row] = on;
}

/* ------------------------------------------------------------------ */
/* mid = projx( mobius_add( 0.27 (x) head, 0.73 (x) tail ) ), D=256    */
/* ------------------------------------------------------------------ */
__global__ __launch_bounds__(256) void mid_kernel(
    const float* __restrict__ head, const float* __restrict__ hn_in,
    const float* __restrict__ tail, const float* __restrict__ tn_in,
    float* __restrict__ mid, float* __restrict__ nout)
{
    __shared__ float sbuf[8];
    const int row = blockIdx.x, tid = threadIdx.x;

    float h = head[(size_t)row * HDIM + tid];
    float t = tail[(size_t)row * HDIM + tid];
    float hn = fmaxf(hn_in[row], NORM_EPS);
    float tn = fmaxf(tn_in[row], NORM_EPS);
    float na = tanhf(0.27f * atanhf(fminf(hn, ART_CLIP)));
    float nc = tanhf(0.73f * atanhf(fminf(tn, ART_CLIP)));
    float a = (na / hn) * h;
    float c = (nc / tn) * t;

    float dot = blockSum(a * c, sbuf);
    float a2 = na * na, c2 = nc * nc;
    float alpha = 1.f + 2.f * dot + c2;
    float beta  = 1.f - a2;
    float den   = fmaxf(1.f + 2.f * dot + a2 * c2, NORM_EPS);
    float z = (alpha * a + beta * c) / den;

    float z2 = blockSum(z * z, sbuf);
    float zn = sqrtf(z2);
    float ps = (zn > MAXNORM) ? (MAXNORM / zn) : 1.f;
    mid[(size_t)row * HDIM + tid] = z * ps;
    if (tid == 0) nout[row] = zn * ps;
}

/* ------------------------------------------------------------------ */
/* Launch                                                              */
/* ------------------------------------------------------------------ */
extern "C" void kernel_launch(void* const* d_in, const int* in_sizes, int n_in,
                              void* d_out, int out_size)
{
    const float* chem = (const float*)d_in[0];
    const float* dpc  = (const float*)d_in[1];
    const float* macc = (const float*)d_in[2];
    const float* ecfp = (const float*)d_in[3];
    const float* esm  = (const float*)d_in[4];
    const float* tpc  = (const float*)d_in[5];
    const float* mer  = (const float*)d_in[6];
    const float* Wd1 = (const float*)d_in[7];  const float* bd1 = (const float*)d_in[8];
    const float* Wd2 = (const float*)d_in[9];  const float* bd2 = (const float*)d_in[10];
    const float* Wd3 = (const float*)d_in[11]; const float* bd3 = (const float*)d_in[12];
    const float* Wt1 = (const float*)d_in[13]; const float* bt1 = (const float*)d_in[14];
    const float* Wt2 = (const float*)d_in[15]; const float* bt2 = (const float*)d_in[16];
    const float* Wt3 = (const float*)d_in[17]; const float* bt3 = (const float*)d_in[18];
    const float* Wm1 = (const float*)d_in[19]; const float* bm1 = (const float*)d_in[20];
    const float* Wm2 = (const float*)d_in[21]; const float* bm2 = (const float*)d_in[22];
    const float* Wm3 = (const float*)d_in[23]; const float* bm3 = (const float*)d_in[24];
    float* outp = (float*)d_out;

    int B = in_sizes[0] / 768;
    if (B > MAXB) B = MAXB;

    __nv_bfloat16 *xh, *xl, *ah, *al, *bh, *bl;
    __nv_bfloat16 *w1h, *w1l, *w2h, *w2l, *w3h, *w3l;
    float *mx, *head, *tail, *mid, *r1, *r2, *na, *nb, *nhead, *ntail, *nmid;
    cudaGetSymbolAddress((void**)&xh,  g_xh);  cudaGetSymbolAddress((void**)&xl,  g_xl);
    cudaGetSymbolAddress((void**)&ah,  g_ah);  cudaGetSymbolAddress((void**)&al,  g_al);
    cudaGetSymbolAddress((void**)&bh,  g_bh);  cudaGetSymbolAddress((void**)&bl,  g_bl);
    cudaGetSymbolAddress((void**)&w1h, g_w1h); cudaGetSymbolAddress((void**)&w1l, g_w1l);
    cudaGetSymbolAddress((void**)&w2h, g_w2h); cudaGetSymbolAddress((void**)&w2l, g_w2l);
    cudaGetSymbolAddress((void**)&w3h, g_w3h); cudaGetSymbolAddress((void**)&w3l, g_w3l);
    cudaGetSymbolAddress((void**)&mx,   g_mx);
    cudaGetSymbolAddress((void**)&head, g_head);
    cudaGetSymbolAddress((void**)&tail, g_tail);
    cudaGetSymbolAddress((void**)&mid,  g_mid);
    cudaGetSymbolAddress((void**)&r1,   g_r1);
    cudaGetSymbolAddress((void**)&r2,   g_r2);
    cudaGetSymbolAddress((void**)&na,   g_na);
    cudaGetSymbolAddress((void**)&nb,   g_nb);
    cudaGetSymbolAddress((void**)&nhead, g_nhead);
    cudaGetSymbolAddress((void**)&ntail, g_ntail);
    cudaGetSymbolAddress((void**)&nmid,  g_nmid);

    cudaFuncSetAttribute(hgemm_kernel,
                         cudaFuncAttributeMaxDynamicSharedMemorySize, HT_SMEM);

    const int D = 1711;
    dim3 tb(32, 8);
    const int MB = B / 128;

    /* =========== DRUG tower =========== */
    wsplit_kernel<<<dim3(KP1 / 32, 1024 / 32), tb>>>(Wd1, D,    1024, KP1,  w1h, w1l);
    wsplit_kernel<<<dim3(1024 / 32, 512 / 32), tb>>>(Wd2, 1024, 512,  1024, w2h, w2l);
    wsplit_kernel<<<dim3(512 / 32,  256 / 32), tb>>>(Wd3, 512,  256,  512,  w3h, w3l);
    prep_kernel<<<B, 256>>>(chem, dpc, macc, ecfp, 768, 11, 167, 765, 4, D, xh, xl, na);

    hgemm_kernel<<<dim3(8, MB), 256, HT_SMEM>>>(xh, xl, KP1, w1h, w1l, KP1, mx, 1024, KP1);
    epi_kernel<<<B, 256>>>(mx, na, bd1, nullptr, ah, al, nhead /*tmp*/, 1024, 1, 1);
    hgemm_kernel<<<dim3(4, MB), 256, HT_SMEM>>>(ah, al, 1024, w2h, w2l, 1024, mx, 512, 1024);
    epi_kernel<<<B, 256>>>(mx, nhead, bd2, nullptr, bh, bl, na, 512, 1, 1);
    hgemm_kernel<<<dim3(2, MB), 256, HT_SMEM>>>(bh, bl, 512, w3h, w3l, 512, mx, 256, 512);
    epi_kernel<<<B, 256>>>(mx, na, bd3, head, nullptr, nullptr, nhead, 256, 0, 0);

    /* =========== TARGET tower (reuses all scratch) =========== */
    wsplit_kernel<<<dim3(KP1 / 32, 1024 / 32), tb>>>(Wt1, D,    1024, KP1,  w1h, w1l);
    wsplit_kernel<<<dim3(1024 / 32, 512 / 32), tb>>>(Wt2, 1024, 512,  1024, w2h, w2l);
    wsplit_kernel<<<dim3(512 / 32,  256 / 32), tb>>>(Wt3, 512,  256,  512,  w3h, w3l);
    prep_kernel<<<B, 256>>>(esm, tpc, mer, mer, 1280, 11, 420, 0, 3, D, xh, xl, nb);

    hgemm_kernel<<<dim3(8, MB), 256, HT_SMEM>>>(xh, xl, KP1, w1h, w1l, KP1, mx, 1024, KP1);
    epi_kernel<<<B, 256>>>(mx, nb, bt1, nullptr, ah, al, ntail /*tmp*/, 1024, 1, 1);
    hgemm_kernel<<<dim3(4, MB), 256, HT_SMEM>>>(ah, al, 1024, w2h, w2l, 1024, mx, 512, 1024);
    epi_kernel<<<B, 256>>>(mx, ntail, bt2, nullptr, bh, bl, nb, 512, 1, 1);
    hgemm_kernel<<<dim3(2, MB), 256, HT_SMEM>>>(bh, bl, 512, w3h, w3l, 512, mx, 256, 512);
    epi_kernel<<<B, 256>>>(mx, nb, bt3, tail, nullptr, nullptr, ntail, 256, 0, 0);

    /* =========== midpoint + mixer (fp32) =========== */
    mid_kernel<<<B, 256>>>(head, nhead, tail, ntail, mid, nmid);

    sgemm_kernel<<<dim3(1, (B + 127) / 128), 256>>>(mid, Wm1, mx, B, 64, 256);
    epi_kernel<<<B, 256>>>(mx, nmid, bm1, r1, nullptr, nullptr, na, 64, 1, 0);
    sgemm_kernel<<<dim3(1, (B + 127) / 128), 256>>>(r1, Wm2, mx, B, 32, 64);
    epi_kernel<<<B, 256>>>(mx, na, bm2, r2, nullptr, nullptr, nb, 32, 1, 0);
    sgemm_kernel<<<dim3(1, (B + 127) / 128), 256>>>(r2, Wm3, mx, B, 2, 32);
    epi_kernel<<<B, 256>>>(mx, nb, bm3, outp, nullptr, nullptr, na, 2, 0, 0);
}